// round 11
// baseline (speedup 1.0000x reference)
#include <cuda_runtime.h>
#include <cuda_fp16.h>
#include <cstdint>
#include <math.h>

#define BB 8
#define TT 16
#define CIN 16
#define HID 64
#define NPIX 4096
#define NOUT (BB*HID*NPIX)

typedef unsigned int u32; typedef unsigned long long u64; typedef unsigned short u16;

// ---------------- device scratch (allocation-free) ----------------
__device__ __align__(16) u32 g_x2[BB*TT*NPIX*CIN];     // x as (lo16<<16|hi16) fp16 pair, [bt][pix][ch]
__device__ __align__(16) u32 g_h2[2][BB*NPIX*HID];     // h state, same packing, [b][pix][ch]
__device__ float g_c[BB*NPIX*HID];                     // c state fp32 [b][pix][ch]
#define BLOB_EL 16896                                  // 192*88 u16 = 33792 B
__device__ __align__(16) u16 g_Bw[20*BLOB_EL];         // 20 blobs: taps 0..8 x {hi,lo}, o-gate {hi,lo}

// ---------------- helpers ----------------
__device__ __forceinline__ u32 s2u(const void* p){u32 a;asm("{ .reg .u64 t; cvta.to.shared.u64 t,%1; cvt.u32.u64 %0,t;}":"=r"(a):"l"(p));return a;}
__device__ __forceinline__ void mb_init(u32 m,u32 c){asm volatile("mbarrier.init.shared.b64 [%0],%1;"::"r"(m),"r"(c):"memory");}
__device__ __forceinline__ void mb_extx(u32 m,u32 b){asm volatile("mbarrier.arrive.expect_tx.shared.b64 _,[%0],%1;"::"r"(m),"r"(b):"memory");}
__device__ __forceinline__ void mb_wait(u32 m,u32 ph){
  u32 done=0;
  while(!done){
    asm volatile("{\n\t.reg .pred p;\n\tmbarrier.try_wait.parity.shared.b64 p,[%1],%2,0x989680;\n\tselp.b32 %0,1,0,p;\n\t}"
                 :"=r"(done):"r"(m),"r"(ph):"memory");
  }
}
__device__ __forceinline__ void cp_bulk(u32 dst,const void* src,u32 bytes,u32 mb){
  asm volatile("cp.async.bulk.shared::cta.global.mbarrier::complete_tx::bytes [%0],[%1],%2,[%3];"
               ::"r"(dst),"l"(src),"r"(bytes),"r"(mb):"memory");
}
#define LDSM4(r,ad) \
  asm volatile("ldmatrix.sync.aligned.m8n8.x4.shared.b16 {%0,%1,%2,%3},[%4];" \
               :"=r"((r)[0]),"=r"((r)[1]),"=r"((r)[2]),"=r"((r)[3]):"r"(ad))
#define MMA(c,a,b0,b1) \
  asm volatile("mma.sync.aligned.m16n8k16.row.col.f32.f16.f16.f32 {%0,%1,%2,%3},{%4,%5,%6,%7},{%8,%9},{%0,%1,%2,%3};" \
               :"+f"((c)[0]),"+f"((c)[1]),"+f"((c)[2]),"+f"((c)[3]) \
               :"r"((a)[0]),"r"((a)[1]),"r"((a)[2]),"r"((a)[3]),"r"(b0),"r"(b1))

__device__ __forceinline__ u32 packh(float v){
  __half h=__float2half_rn(v);
  u16 hb=__half_as_ushort(h);
  u16 lb=__half_as_ushort(__float2half_rn(v-__half2float(h)));
  return ((u32)lb<<16)|hb;
}

// ---------------- prep kernels ----------------
__global__ void prep_w(const float* __restrict__ Wf,const float* __restrict__ Wi,
                       const float* __restrict__ Wc,const float* __restrict__ Wo){
  int id=blockIdx.x*blockDim.x+threadIdx.x;
  if(id>=20*BLOB_EL) return;
  int k=id%88, n=(id/88)%192, j=id/BLOB_EL;
  float v=0.f;
  if(k<80){
    if(j<18){
      int tap=j>>1, gate=n>>6, oc=n&63;
      if(gate==0) v=Wf[(oc*80+k)*9+tap];
      else if(gate==1) v=Wi[(oc*80+k)*9+tap];
      else v=Wc[(oc*80+k)*9+tap];
    } else if(n<64){
      v=Wo[n*80+k];
    }
  }
  __half h=__float2half_rn(v);
  u16 val=((j&1)==0)?__half_as_ushort(h):__half_as_ushort(__float2half_rn(v-__half2float(h)));
  g_Bw[id]=val;
}

__global__ void prep_x(const float* __restrict__ x){
  int id=blockIdx.x*blockDim.x+threadIdx.x;
  if(id>=BB*TT*NPIX*CIN) return;
  int c=id&15, pix=(id>>4)&4095, bt=id>>16;
  g_x2[id]=packh(x[((size_t)bt*16+c)*4096+pix]);
}

__global__ void zero_hc(){
  int id=blockIdx.x*blockDim.x+threadIdx.x;
  if(id<BB*NPIX*HID){ g_h2[0][id]=0u; g_c[id]=0.f; }
}

// ---------------- fused step kernel ----------------
// smem: A-hi [264][88]u16 @0 (46464B), A-lo @46464, ring 4x33792 @92928, mbar @228096
#define A_LO   46464
#define RING   92928
#define BLOB   33792
#define MB_OFF 228096
#define SMEMSZ 228128

__global__ __launch_bounds__(512,1) void step_kernel(int t,int src,
     const float* __restrict__ bfp,const float* __restrict__ bip,
     const float* __restrict__ bcp,const float* __restrict__ bop,
     float* __restrict__ out)
{
  extern __shared__ __align__(1024) unsigned char smem[];
  const u32 sb=s2u(smem);
  const int tid=threadIdx.x, lane=tid&31, wid=tid>>5;
  const int blk=blockIdx.x, b=blk>>5, ty=blk&31;
  const int pixbase=ty*128;
  const int dst=src^1;
  const u32 mb=sb+MB_OFF;

  // ---- tid0: init mbarriers + prime ring slots 0..3 with blobs 0..3 ----
  if(tid==0){
    for(int m=0;m<4;m++) mb_init(mb+8*m,1);
    for(int j=0;j<4;j++){
      mb_extx(mb+8*j,BLOB);
      cp_bulk(sb+RING+(u32)j*BLOB,(const void*)(g_Bw+(size_t)j*BLOB_EL),BLOB,mb+8*j);
    }
  }

  // ---- stage A patch: 4 rows x 66 cols x 80 ch, hi/lo fp16 planes ----
  {
    u16* aHi=(u16*)smem;
    u16* aLo=(u16*)(smem+A_LO);
    for(int id=tid; id<264*80; id+=512){
      int s=id/80, ch=id-80*s;
      int r=s/66, c2=s-66*r;
      int gy=ty*2-1+r, gx=c2-1;
      u32 v=0u;
      if((unsigned)gy<64u && (unsigned)gx<64u){
        int pix=gy*64+gx;
        v=(ch<16)? g_x2[((size_t)(b*16+t)*4096+pix)*16+ch]
                 : g_h2[src][((size_t)b*4096+pix)*64+(ch-16)];
      }
      aHi[s*88+ch]=(u16)(v&0xffffu);
      aLo[s*88+ch]=(u16)(v>>16);
    }
  }
  __syncthreads();

  // ---- warp roles: 4 warpM (32 pix) x 4 warpN ----
  const int warpM=wid>>2;
  const int warpN=(warpM+(wid&3))&3;
  const u32 aofs=(u32)((lane&15)*176+(lane>>4)*16);
  const u32 bofs=(u32)(((lane&7)+((lane>>4)&1)*8)*176+((lane>>3)&1)*16);
  u32 hofs[2];
#pragma unroll
  for(int half=0;half<2;half++){
    int m0=warpM*32+half*16;
    hofs[half]=(u32)(((m0>>6)*66+(m0&63))*176)+aofs;
  }

  // acc[half][q][4]: q 0..5 conv (3 ntile x 2 n8), q 6..7 o-gate
  float acc[2][8][4];
#pragma unroll
  for(int h2=0;h2<2;h2++)
#pragma unroll
    for(int q=0;q<8;q++)
#pragma unroll
      for(int e=0;e<4;e++) acc[h2][q][e]=0.f;

  // ---- main loop: 10 phases (9 conv taps + o-gate), pair of blobs each ----
  for(int m=0;m<10;m++){
    const int j0=2*m, j1=j0+1;
    mb_wait(mb+8*(u32)(j0&3),(u32)((j0>>2)&1));
    mb_wait(mb+8*(u32)(j1&3),(u32)((j1>>2)&1));
    const u32 bb0=sb+RING+(u32)(j0&3)*BLOB;
    const u32 bb1=sb+RING+(u32)(j1&3)*BLOB;
    int dy,dx,ntile,nbase,qb;
    if(m<9){ dy=m/3-1; dx=m%3-1; ntile=3; nbase=warpN*48; qb=0; }
    else   { dy=0; dx=0; ntile=1; nbase=warpN*16; qb=6; }
    const u32 taprow=(u32)(((dy+1)*66+(dx+1))*176);

#pragma unroll
    for(int kc=0;kc<5;kc++){
      u32 ah[2][4], al[2][4];
#pragma unroll
      for(int half=0;half<2;half++){
        const u32 aa=hofs[half]+taprow+(u32)kc*32u;
        LDSM4(ah[half], sb+aa);
        LDSM4(al[half], sb+A_LO+aa);
      }
#pragma unroll
      for(int tt=0;tt<3;tt++){
        if(tt>=ntile) break;
        u32 bh[4], bl[4];
        const u32 bo2=(u32)(nbase+tt*16)*176u+(u32)kc*32u+bofs;
        LDSM4(bh, bb0+bo2);
        LDSM4(bl, bb1+bo2);
        const int q0=qb+2*tt, q1=q0+1;
#pragma unroll
        for(int half=0;half<2;half++){
          MMA(acc[half][q0], ah[half], bh[0],bh[1]);
          MMA(acc[half][q1], ah[half], bh[2],bh[3]);
          MMA(acc[half][q0], ah[half], bl[0],bl[1]);
          MMA(acc[half][q1], ah[half], bl[2],bl[3]);
          MMA(acc[half][q0], al[half], bh[0],bh[1]);
          MMA(acc[half][q1], al[half], bh[2],bh[3]);
        }
      }
    }
    __syncthreads();
    if(tid==0){
#pragma unroll
      for(int d=4;d<6;d++){
        int j=2*m+d;
        if(j<20){
          mb_extx(mb+8*(u32)(j&3),BLOB);
          cp_bulk(sb+RING+(u32)(j&3)*BLOB,(const void*)(g_Bw+(size_t)j*BLOB_EL),BLOB,mb+8*(u32)(j&3));
        }
      }
    }
  }

  // ---- cross-warp gate exchange via smem (reuse A/ring region) ----
  float* sg=(float*)smem;   // [128 pix][256 n] f32 = 131072 B
#pragma unroll
  for(int half=0;half<2;half++)
#pragma unroll
    for(int q=0;q<8;q++)
#pragma unroll
      for(int e=0;e<4;e++){
        int pix=warpM*32+half*16+(lane>>2)+((e>>1)*8);
        int n=(q<6)? (warpN*48+(q>>1)*16+(q&1)*8+(lane&3)*2+(e&1))
                   : (192+warpN*16+(q&1)*8+(lane&3)*2+(e&1));
        sg[pix*256+n]=acc[half][q][e];
      }
  __syncthreads();

  // ---- fused LSTM update ----
  {
    const int oc=tid&63;
    const float bfv=bfp[oc], biv=bip[oc], bcv=bcp[oc], bov=bop[oc];
    for(int it=tid; it<8192; it+=512){
      int pix=it>>6;
      float f =sg[pix*256+oc];
      float i2=sg[pix*256+64+oc];
      float gg=sg[pix*256+128+oc];
      float oo=sg[pix*256+192+oc];
      f =1.f/(1.f+__expf(-(f +bfv)));
      i2=1.f/(1.f+__expf(-(i2+biv)));
      gg=2.f/(1.f+__expf(-2.f*(gg+bcv)))-1.f;
      oo=1.f/(1.f+__expf(-(oo+bov)));
      int pixg=pixbase+pix;
      size_t ci=((size_t)b*4096+pixg)*64+oc;
      float cn=g_c[ci]*f+i2*gg;
      g_c[ci]=cn;
      float hh=(2.f/(1.f+__expf(-2.f*cn))-1.f)*oo;
      if(t<TT-1){
        g_h2[dst][ci]=packh(hh);
      } else {
        out[((size_t)(b*64+oc))*4096+pixg]=hh;
        out[(size_t)NOUT+((size_t)(b*64+oc))*4096+pixg]=cn;
      }
    }
  }
}

// ---------------- host launch ----------------
extern "C" void kernel_launch(void* const* d_in, const int* in_sizes, int n_in,
                              void* d_out, int out_size)
{
  const float* x  =(const float*)d_in[0];
  const float* Wf =(const float*)d_in[1];
  const float* bf =(const float*)d_in[2];
  const float* Wi =(const float*)d_in[3];
  const float* bi =(const float*)d_in[4];
  const float* Wc =(const float*)d_in[5];
  const float* bc =(const float*)d_in[6];
  const float* Wo =(const float*)d_in[7];
  const float* bo =(const float*)d_in[8];
  float* out=(float*)d_out;

  cudaFuncSetAttribute(step_kernel, cudaFuncAttributeMaxDynamicSharedMemorySize, SMEMSZ);

  prep_w<<<(20*BLOB_EL+255)/256,256>>>(Wf,Wi,Wc,Wo);
  prep_x<<<(BB*TT*NPIX*CIN+255)/256,256>>>(x);
  zero_hc<<<(BB*NPIX*HID+255)/256,256>>>();

  for(int t=0;t<TT;t++){
    step_kernel<<<256,512,SMEMSZ>>>(t, t&1, bf,bi,bc,bo, out);
  }
}

// round 13
// speedup vs baseline: 1.5377x; 1.5377x over previous
#include <cuda_runtime.h>
#include <cuda_fp16.h>
#include <cstdint>
#include <math.h>

#define BB 8
#define TT 16
#define CIN 16
#define HID 64
#define NPIX 4096
#define NOUT (BB*HID*NPIX)

typedef unsigned int u32; typedef unsigned long long u64; typedef unsigned short u16;

// ---------------- device scratch (allocation-free) ----------------
__device__ __align__(16) u32 g_x2[BB*TT*NPIX*CIN];     // x as (lo16<<16|hi16) fp16 pair, [bt][pix][ch]
__device__ __align__(16) u32 g_h2[2][BB*NPIX*HID];     // h state, same packing, [b][pix][ch]
__device__ float g_c[BB*NPIX*HID];                     // c state fp32 [b][pix][ch]
#define BLOB_EL 16896                                  // 192*88 u16 = 33792 B
__device__ __align__(16) u16 g_Bw[20*BLOB_EL];         // 20 blobs: taps 0..8 x {hi,lo}, o-gate {hi,lo}

// ---------------- helpers ----------------
__device__ __forceinline__ u32 s2u(const void* p){u32 a;asm("{ .reg .u64 t; cvta.to.shared.u64 t,%1; cvt.u32.u64 %0,t;}":"=r"(a):"l"(p));return a;}
__device__ __forceinline__ void mb_init(u32 m,u32 c){asm volatile("mbarrier.init.shared.b64 [%0],%1;"::"r"(m),"r"(c):"memory");}
__device__ __forceinline__ void mb_extx(u32 m,u32 b){asm volatile("mbarrier.arrive.expect_tx.shared.b64 _,[%0],%1;"::"r"(m),"r"(b):"memory");}
__device__ __forceinline__ void mb_wait(u32 m,u32 ph){
  u32 done=0;
  while(!done){
    asm volatile("{\n\t.reg .pred p;\n\tmbarrier.try_wait.parity.shared.b64 p,[%1],%2,0x989680;\n\tselp.b32 %0,1,0,p;\n\t}"
                 :"=r"(done):"r"(m),"r"(ph):"memory");
  }
}
__device__ __forceinline__ void cp_bulk(u32 dst,const void* src,u32 bytes,u32 mb){
  asm volatile("cp.async.bulk.shared::cta.global.mbarrier::complete_tx::bytes [%0],[%1],%2,[%3];"
               ::"r"(dst),"l"(src),"r"(bytes),"r"(mb):"memory");
}
#define LDSM4(r,ad) \
  asm volatile("ldmatrix.sync.aligned.m8n8.x4.shared.b16 {%0,%1,%2,%3},[%4];" \
               :"=r"((r)[0]),"=r"((r)[1]),"=r"((r)[2]),"=r"((r)[3]):"r"(ad))
#define MMA(c,a,b0,b1) \
  asm volatile("mma.sync.aligned.m16n8k16.row.col.f32.f16.f16.f32 {%0,%1,%2,%3},{%4,%5,%6,%7},{%8,%9},{%0,%1,%2,%3};" \
               :"+f"((c)[0]),"+f"((c)[1]),"+f"((c)[2]),"+f"((c)[3]) \
               :"r"((a)[0]),"r"((a)[1]),"r"((a)[2]),"r"((a)[3]),"r"(b0),"r"(b1))

__device__ __forceinline__ u32 packh(float v){
  __half h=__float2half_rn(v);
  u16 hb=__half_as_ushort(h);
  u16 lb=__half_as_ushort(__float2half_rn(v-__half2float(h)));
  return ((u32)lb<<16)|hb;
}

// ---------------- prep kernels ----------------
__global__ void prep_w(const float* __restrict__ Wf,const float* __restrict__ Wi,
                       const float* __restrict__ Wc,const float* __restrict__ Wo){
  int id=blockIdx.x*blockDim.x+threadIdx.x;
  if(id>=20*BLOB_EL) return;
  int k=id%88, n=(id/88)%192, j=id/BLOB_EL;
  float v=0.f;
  if(k<80){
    if(j<18){
      int tap=j>>1, gate=n>>6, oc=n&63;
      if(gate==0) v=Wf[(oc*80+k)*9+tap];
      else if(gate==1) v=Wi[(oc*80+k)*9+tap];
      else v=Wc[(oc*80+k)*9+tap];
    } else if(n<64){
      v=Wo[n*80+k];
    }
  }
  __half h=__float2half_rn(v);
  u16 val=((j&1)==0)?__half_as_ushort(h):__half_as_ushort(__float2half_rn(v-__half2float(h)));
  g_Bw[id]=val;
}

__global__ void prep_x(const float* __restrict__ x){
  int id=blockIdx.x*blockDim.x+threadIdx.x;
  if(id>=BB*TT*NPIX*CIN) return;
  int c=id&15, pix=(id>>4)&4095, bt=id>>16;
  g_x2[id]=packh(x[((size_t)bt*16+c)*4096+pix]);
}

__global__ void zero_hc(){
  int id=blockIdx.x*blockDim.x+threadIdx.x;
  if(id<BB*NPIX*HID){ g_h2[0][id]=0u; g_c[id]=0.f; }
}

// ---------------- fused step kernel ----------------
// smem: A-hi [264][88]u16 @0 (46464B), A-lo @46464, ring 4x33792 @92928, mbar @228096
#define A_LO   46464
#define RING   92928
#define BLOB   33792
#define MB_OFF 228096
#define SMEMSZ 228128

__global__ __launch_bounds__(512,1) void step_kernel(int t,int src,
     const float* __restrict__ bfp,const float* __restrict__ bip,
     const float* __restrict__ bcp,const float* __restrict__ bop,
     float* __restrict__ out)
{
  extern __shared__ __align__(1024) unsigned char smem[];
  const u32 sb=s2u(smem);
  const int tid=threadIdx.x, lane=tid&31, wid=tid>>5;
  const int blk=blockIdx.x, b=blk>>5, ty=blk&31;
  const int pixbase=ty*128;
  const int dst=src^1;
  const u32 mb=sb+MB_OFF;

  // ---- tid0: init mbarriers + prime ring slots 0..3 with blobs 0..3 ----
  if(tid==0){
    for(int m=0;m<4;m++) mb_init(mb+8*m,1);
    for(int j=0;j<4;j++){
      mb_extx(mb+8*j,BLOB);
      cp_bulk(sb+RING+(u32)j*BLOB,(const void*)(g_Bw+(size_t)j*BLOB_EL),BLOB,mb+8*j);
    }
  }

  // ---- stage A patch: 4 rows x 66 cols x 80 ch, hi/lo fp16 planes ----
  {
    u16* aHi=(u16*)smem;
    u16* aLo=(u16*)(smem+A_LO);
    for(int id=tid; id<264*80; id+=512){
      int s=id/80, ch=id-80*s;
      int r=s/66, c2=s-66*r;
      int gy=ty*2-1+r, gx=c2-1;
      u32 v=0u;
      if((unsigned)gy<64u && (unsigned)gx<64u){
        int pix=gy*64+gx;
        v=(ch<16)? g_x2[((size_t)(b*16+t)*4096+pix)*16+ch]
                 : g_h2[src][((size_t)b*4096+pix)*64+(ch-16)];
      }
      aHi[s*88+ch]=(u16)(v&0xffffu);
      aLo[s*88+ch]=(u16)(v>>16);
    }
  }
  __syncthreads();

  // ---- warp roles: 4 warpM (32 pix) x 4 warpN ----
  const int warpM=wid>>2;
  const int warpN=(warpM+(wid&3))&3;
  const u32 aofs=(u32)((lane&15)*176+(lane>>4)*16);
  const u32 bofs=(u32)(((lane&7)+((lane>>4)&1)*8)*176+((lane>>3)&1)*16);
  u32 hofs[2];
#pragma unroll
  for(int half=0;half<2;half++){
    int m0=warpM*32+half*16;
    hofs[half]=(u32)(((m0>>6)*66+(m0&63))*176)+aofs;
  }

  // conv accumulators (static indices only!) + o-gate accumulators
  float accc[2][6][4];
  float acco[2][2][4];
#pragma unroll
  for(int h2=0;h2<2;h2++){
#pragma unroll
    for(int q=0;q<6;q++)
#pragma unroll
      for(int e=0;e<4;e++) accc[h2][q][e]=0.f;
#pragma unroll
    for(int q=0;q<2;q++)
#pragma unroll
      for(int e=0;e<4;e++) acco[h2][q][e]=0.f;
  }

  // ---- conv taps: 9 phases, blob pair (hi,lo) each ----
  for(int m=0;m<9;m++){
    const int j0=2*m, j1=j0+1;
    mb_wait(mb+8*(u32)(j0&3),(u32)((j0>>2)&1));
    mb_wait(mb+8*(u32)(j1&3),(u32)((j1>>2)&1));
    const u32 bb0=sb+RING+(u32)(j0&3)*BLOB;
    const u32 bb1=sb+RING+(u32)(j1&3)*BLOB;
    const int dy=m/3-1, dx=m%3-1;
    const u32 taprow=(u32)(((dy+1)*66+(dx+1))*176);

#pragma unroll
    for(int kc=0;kc<5;kc++){
      u32 ah[2][4], al[2][4];
#pragma unroll
      for(int half=0;half<2;half++){
        const u32 aa=hofs[half]+taprow+(u32)kc*32u;
        LDSM4(ah[half], sb+aa);
        LDSM4(al[half], sb+A_LO+aa);
      }
#pragma unroll
      for(int tt=0;tt<3;tt++){
        u32 bh[4], bl[4];
        const u32 bo2=(u32)(warpN*48+tt*16)*176u+(u32)kc*32u+bofs;
        LDSM4(bh, bb0+bo2);
        LDSM4(bl, bb1+bo2);
#pragma unroll
        for(int half=0;half<2;half++){
          MMA(accc[half][2*tt],   ah[half], bh[0],bh[1]);
          MMA(accc[half][2*tt+1], ah[half], bh[2],bh[3]);
          MMA(accc[half][2*tt],   ah[half], bl[0],bl[1]);
          MMA(accc[half][2*tt+1], ah[half], bl[2],bl[3]);
          MMA(accc[half][2*tt],   al[half], bh[0],bh[1]);
          MMA(accc[half][2*tt+1], al[half], bh[2],bh[3]);
        }
      }
    }
    __syncthreads();
    if(tid==0){
#pragma unroll
      for(int d=4;d<6;d++){
        int j=2*m+d;
        if(j<20){
          mb_extx(mb+8*(u32)(j&3),BLOB);
          cp_bulk(sb+RING+(u32)(j&3)*BLOB,(const void*)(g_Bw+(size_t)j*BLOB_EL),BLOB,mb+8*(u32)(j&3));
        }
      }
    }
  }

  // ---- o-gate phase: blobs 18 (hi) and 19 (lo), center-tap A, N=64 ----
  {
    const int j0=18, j1=19;
    mb_wait(mb+8*(u32)(j0&3),(u32)((j0>>2)&1));
    mb_wait(mb+8*(u32)(j1&3),(u32)((j1>>2)&1));
    const u32 bb0=sb+RING+(u32)(j0&3)*BLOB;
    const u32 bb1=sb+RING+(u32)(j1&3)*BLOB;
    const u32 taprow=(u32)((1*66+1)*176);
#pragma unroll
    for(int kc=0;kc<5;kc++){
      u32 ah[2][4], al[2][4];
#pragma unroll
      for(int half=0;half<2;half++){
        const u32 aa=hofs[half]+taprow+(u32)kc*32u;
        LDSM4(ah[half], sb+aa);
        LDSM4(al[half], sb+A_LO+aa);
      }
      u32 bh[4], bl[4];
      const u32 bo2=(u32)(warpN*16)*176u+(u32)kc*32u+bofs;
      LDSM4(bh, bb0+bo2);
      LDSM4(bl, bb1+bo2);
#pragma unroll
      for(int half=0;half<2;half++){
        MMA(acco[half][0], ah[half], bh[0],bh[1]);
        MMA(acco[half][1], ah[half], bh[2],bh[3]);
        MMA(acco[half][0], ah[half], bl[0],bl[1]);
        MMA(acco[half][1], ah[half], bl[2],bl[3]);
        MMA(acco[half][0], al[half], bh[0],bh[1]);
        MMA(acco[half][1], al[half], bh[2],bh[3]);
      }
    }
    __syncthreads();
  }

  // ---- cross-warp gate exchange via smem (reuse A/ring region) ----
  float* sg=(float*)smem;   // [128 pix][256 n] f32 = 131072 B
#pragma unroll
  for(int half=0;half<2;half++){
#pragma unroll
    for(int q=0;q<6;q++)
#pragma unroll
      for(int e=0;e<4;e++){
        int pix=warpM*32+half*16+(lane>>2)+((e>>1)*8);
        int n=warpN*48+(q>>1)*16+(q&1)*8+(lane&3)*2+(e&1);
        sg[pix*256+n]=accc[half][q][e];
      }
#pragma unroll
    for(int q=0;q<2;q++)
#pragma unroll
      for(int e=0;e<4;e++){
        int pix=warpM*32+half*16+(lane>>2)+((e>>1)*8);
        int n=192+warpN*16+q*8+(lane&3)*2+(e&1);
        sg[pix*256+n]=acco[half][q][e];
      }
  }
  __syncthreads();

  // ---- fused LSTM update ----
  {
    const int oc=tid&63;
    const float bfv=bfp[oc], biv=bip[oc], bcv=bcp[oc], bov=bop[oc];
    for(int it=tid; it<8192; it+=512){
      int pix=it>>6;
      float f =sg[pix*256+oc];
      float i2=sg[pix*256+64+oc];
      float gg=sg[pix*256+128+oc];
      float oo=sg[pix*256+192+oc];
      f =1.f/(1.f+__expf(-(f +bfv)));
      i2=1.f/(1.f+__expf(-(i2+biv)));
      gg=2.f/(1.f+__expf(-2.f*(gg+bcv)))-1.f;
      oo=1.f/(1.f+__expf(-(oo+bov)));
      int pixg=pixbase+pix;
      size_t ci=((size_t)b*4096+pixg)*64+oc;
      float cn=g_c[ci]*f+i2*gg;
      g_c[ci]=cn;
      float hh=(2.f/(1.f+__expf(-2.f*cn))-1.f)*oo;
      if(t<TT-1){
        g_h2[dst][ci]=packh(hh);
      } else {
        out[((size_t)(b*64+oc))*4096+pixg]=hh;
        out[(size_t)NOUT+((size_t)(b*64+oc))*4096+pixg]=cn;
      }
    }
  }
}

// ---------------- host launch ----------------
extern "C" void kernel_launch(void* const* d_in, const int* in_sizes, int n_in,
                              void* d_out, int out_size)
{
  const float* x  =(const float*)d_in[0];
  const float* Wf =(const float*)d_in[1];
  const float* bf =(const float*)d_in[2];
  const float* Wi =(const float*)d_in[3];
  const float* bi =(const float*)d_in[4];
  const float* Wc =(const float*)d_in[5];
  const float* bc =(const float*)d_in[6];
  const float* Wo =(const float*)d_in[7];
  const float* bo =(const float*)d_in[8];
  float* out=(float*)d_out;

  cudaFuncSetAttribute(step_kernel, cudaFuncAttributeMaxDynamicSharedMemorySize, SMEMSZ);

  prep_w<<<(20*BLOB_EL+255)/256,256>>>(Wf,Wi,Wc,Wo);
  prep_x<<<(BB*TT*NPIX*CIN+255)/256,256>>>(x);
  zero_hc<<<(BB*NPIX*HID+255)/256,256>>>();

  for(int t=0;t<TT;t++){
    step_kernel<<<256,512,SMEMSZ>>>(t, t&1, bf,bi,bc,bo, out);
  }
}

// round 14
// speedup vs baseline: 1.9459x; 1.2654x over previous
#include <cuda_runtime.h>
#include <cuda_fp16.h>
#include <cstdint>
#include <math.h>

#define BB 8
#define TT 16
#define CIN 16
#define HID 64
#define NPIX 4096
#define NOUT (BB*HID*NPIX)

typedef unsigned int u32; typedef unsigned long long u64; typedef unsigned short u16;

// ---------------- device scratch (allocation-free) ----------------
__device__ __align__(16) u32 g_x2[BB*TT*NPIX*CIN];     // x as (lo16<<16|hi16) fp16 pair, [bt][pix][ch]
__device__ __align__(16) u32 g_h2[2][BB*NPIX*HID];     // h state, same packing, [b][pix][ch]
__device__ float g_c[BB*NPIX*HID];                     // c state fp32 [b][pix][ch]
#define BLOB_EL 22528                                  // 256*88 u16 = 45056 B
__device__ __align__(16) u16 g_Bw[18*BLOB_EL];         // 18 blobs: [tap*2+term][n(256)][k(88)]

// ---------------- helpers ----------------
__device__ __forceinline__ u32 s2u(const void* p){u32 a;asm("{ .reg .u64 t; cvta.to.shared.u64 t,%1; cvt.u32.u64 %0,t;}":"=r"(a):"l"(p));return a;}
__device__ __forceinline__ void mb_init(u32 m,u32 c){asm volatile("mbarrier.init.shared.b64 [%0],%1;"::"r"(m),"r"(c):"memory");}
__device__ __forceinline__ void mb_extx(u32 m,u32 b){asm volatile("mbarrier.arrive.expect_tx.shared.b64 _,[%0],%1;"::"r"(m),"r"(b):"memory");}
__device__ __forceinline__ void mb_arrive(u32 m){asm volatile("mbarrier.arrive.shared.b64 _,[%0];"::"r"(m):"memory");}
__device__ __forceinline__ void mb_wait(u32 m,u32 ph){
  u32 done=0;
  while(!done){
    asm volatile("{\n\t.reg .pred p;\n\tmbarrier.try_wait.parity.shared.b64 p,[%1],%2,0x989680;\n\tselp.b32 %0,1,0,p;\n\t}"
                 :"=r"(done):"r"(m),"r"(ph):"memory");
  }
}
__device__ __forceinline__ void cp_bulk(u32 dst,const void* src,u32 bytes,u32 mb){
  asm volatile("cp.async.bulk.shared::cta.global.mbarrier::complete_tx::bytes [%0],[%1],%2,[%3];"
               ::"r"(dst),"l"(src),"r"(bytes),"r"(mb):"memory");
}
#define LDSM4(r,ad) \
  asm volatile("ldmatrix.sync.aligned.m8n8.x4.shared.b16 {%0,%1,%2,%3},[%4];" \
               :"=r"((r)[0]),"=r"((r)[1]),"=r"((r)[2]),"=r"((r)[3]):"r"(ad))
#define MMA(c,a,b0,b1) \
  asm volatile("mma.sync.aligned.m16n8k16.row.col.f32.f16.f16.f32 {%0,%1,%2,%3},{%4,%5,%6,%7},{%8,%9},{%0,%1,%2,%3};" \
               :"+f"((c)[0]),"+f"((c)[1]),"+f"((c)[2]),"+f"((c)[3]) \
               :"r"((a)[0]),"r"((a)[1]),"r"((a)[2]),"r"((a)[3]),"r"(b0),"r"(b1))

__device__ __forceinline__ u32 packh(float v){
  __half h=__float2half_rn(v);
  u16 hb=__half_as_ushort(h);
  u16 lb=__half_as_ushort(__float2half_rn(v-__half2float(h)));
  return ((u32)lb<<16)|hb;
}

// ---------------- prep kernels ----------------
__global__ void prep_w(const float* __restrict__ Wf,const float* __restrict__ Wi,
                       const float* __restrict__ Wc,const float* __restrict__ Wo){
  int id=blockIdx.x*blockDim.x+threadIdx.x;
  if(id>=18*BLOB_EL) return;
  int k=id%88, n=(id/88)&255, j=id/BLOB_EL;
  int tap=j>>1, term=j&1;
  float v=0.f;
  if(k<80 && (n<192 || tap==4)){
    int gate=n>>6, oc=n&63;
    if(gate==0) v=Wf[(oc*80+k)*9+tap];
    else if(gate==1) v=Wi[(oc*80+k)*9+tap];
    else if(gate==2) v=Wc[(oc*80+k)*9+tap];
    else v=Wo[oc*80+k];
  }
  __half h=__float2half_rn(v);
  u16 val=(term==0)?__half_as_ushort(h):__half_as_ushort(__float2half_rn(v-__half2float(h)));
  g_Bw[id]=val;
}

__global__ void prep_x(const float* __restrict__ x){
  int id=blockIdx.x*blockDim.x+threadIdx.x;
  if(id>=BB*TT*NPIX*CIN) return;
  int c=id&15, pix=(id>>4)&4095, bt=id>>16;
  g_x2[id]=packh(x[((size_t)bt*16+c)*4096+pix]);
}

__global__ void zero_hc(){
  int id=blockIdx.x*blockDim.x+threadIdx.x;
  if(id<BB*NPIX*HID){ g_h2[0][id]=0u; g_c[id]=0.f; }
}

// ---------------- fused step kernel ----------------
// smem: A-hi [264][88]u16 @0 (46464B), A-lo @46464, ring 3x45056 @92928,
//       full mbar[3] @228096, empty mbar[3] @228120
#define A_LO   46464
#define RING   92928
#define BLOB   45056
#define MB_F   228096
#define MB_E   228120
#define SMEMSZ 228144

__global__ __launch_bounds__(512,1) void step_kernel(int t,int src,
     const float* __restrict__ bfp,const float* __restrict__ bip,
     const float* __restrict__ bcp,const float* __restrict__ bop,
     float* __restrict__ out)
{
  extern __shared__ __align__(1024) unsigned char smem[];
  const u32 sb=s2u(smem);
  const int tid=threadIdx.x, lane=tid&31, wid=tid>>5;
  const int blk=blockIdx.x, b=blk>>5, ty=blk&31;
  const int pixbase=ty*128;
  const int dst=src^1;

  // ---- init barriers, then prime ring (overlapped with A staging) ----
  if(tid==0){
    for(int m=0;m<3;m++){ mb_init(sb+MB_F+8*m,1); mb_init(sb+MB_E+8*m,16); }
  }
  __syncthreads();
  if(tid==0){
    for(int j=0;j<3;j++){
      mb_extx(sb+MB_F+8*j,BLOB);
      cp_bulk(sb+RING+(u32)j*BLOB,(const void*)(g_Bw+(size_t)j*BLOB_EL),BLOB,sb+MB_F+8*j);
    }
  }

  // ---- stage A patch: 4 rows x 66 cols x 80 ch, hi/lo fp16 planes ----
  {
    u16* aHi=(u16*)smem;
    u16* aLo=(u16*)(smem+A_LO);
    for(int id=tid; id<264*80; id+=512){
      int s=id/80, ch=id-80*s;
      int r=s/66, c2=s-66*r;
      int gy=ty*2-1+r, gx=c2-1;
      u32 v=0u;
      if((unsigned)gy<64u && (unsigned)gx<64u){
        int pix=gy*64+gx;
        v=(ch<16)? g_x2[((size_t)(b*16+t)*4096+pix)*16+ch]
                 : g_h2[src][((size_t)b*4096+pix)*64+(ch-16)];
      }
      aHi[s*88+ch]=(u16)(v&0xffffu);
      aLo[s*88+ch]=(u16)(v>>16);
    }
  }
  __syncthreads();

  // ---- warp roles: warpM = wid>>2 (32 pix), warpN = (warpM + wid&3)&3 ----
  const int warpM=wid>>2;
  const int warpN=(warpM+(wid&3))&3;
  int nb[4];
  if(warpN<2){ nb[0]=warpN*64; nb[1]=nb[0]+16; nb[2]=nb[0]+32; nb[3]=nb[0]+48; }
  else { int g0=128+(warpN-2)*32, o0=192+(warpN-2)*32;
         nb[0]=g0; nb[1]=g0+16; nb[2]=o0; nb[3]=o0+16; }
  const u32 aofs=(u32)((lane&15)*176+(lane>>4)*16);
  const u32 bofs=(u32)(((lane&7)+((lane>>4)&1)*8)*176+((lane>>3)&1)*16);
  u32 hofs[2];
#pragma unroll
  for(int half=0;half<2;half++){
    int m0=warpM*32+half*16;
    hofs[half]=(u32)(((m0>>6)*66+(m0&63))*176)+aofs;
  }

  float acc[2][8][4];
#pragma unroll
  for(int h2=0;h2<2;h2++)
#pragma unroll
    for(int q=0;q<8;q++)
#pragma unroll
      for(int e=0;e<4;e++) acc[h2][q][e]=0.f;

  // ---- main loop: 18 blobs, producer-consumer (no block-wide syncs) ----
  for(int j=0;j<18;j++){
    const int slot=j%3, r3=j/3, tap=j>>1;
    mb_wait(sb+MB_F+8*(u32)slot,(u32)(r3&1));
    const u32 bb=sb+RING+(u32)slot*BLOB;
    const int dy=tap/3-1, dx=tap%3-1;
    const u32 taprow=(u32)(((dy+1)*66+(dx+1))*176);
    const int npA=(warpN<2||tap==4)?4:2;
    const int nterm=(j&1)?1:2;
#pragma unroll
    for(int s=0;s<2;s++){
      if(s>=nterm) break;
      const u32 aplane=sb+(((j&1)==0&&s==1)?A_LO:0u);
#pragma unroll
      for(int kc=0;kc<5;kc++){
        u32 bf_[4][4];
#pragma unroll
        for(int p=0;p<4;p++){
          if(p<npA){
            LDSM4(bf_[p], bb+(u32)nb[p]*176u+(u32)kc*32u+bofs);
          }
        }
#pragma unroll
        for(int half=0;half<2;half++){
          u32 a4[4];
          LDSM4(a4, aplane+hofs[half]+taprow+(u32)kc*32u);
#pragma unroll
          for(int p=0;p<4;p++){
            if(p<npA){
              MMA(acc[half][2*p],   a4, bf_[p][0],bf_[p][1]);
              MMA(acc[half][2*p+1], a4, bf_[p][2],bf_[p][3]);
            }
          }
        }
      }
    }
    if(lane==0) mb_arrive(sb+MB_E+8*(u32)slot);
    if(wid==slot && lane==0 && j+3<18){
      mb_wait(sb+MB_E+8*(u32)slot,(u32)(r3&1));
      mb_extx(sb+MB_F+8*(u32)slot,BLOB);
      cp_bulk(bb,(const void*)(g_Bw+(size_t)(j+3)*BLOB_EL),BLOB,sb+MB_F+8*(u32)slot);
    }
  }

  // ---- cross-warp gate exchange via smem (reuse A/ring region) ----
  __syncthreads();
  float* sg=(float*)smem;   // [128 pix][256 n] f32 = 131072 B
#pragma unroll
  for(int half=0;half<2;half++)
#pragma unroll
    for(int q=0;q<8;q++)
#pragma unroll
      for(int e=0;e<4;e++){
        int pix=warpM*32+half*16+(lane>>2)+((e>>1)*8);
        int n=nb[q>>1]+(q&1)*8+(lane&3)*2+(e&1);
        sg[pix*256+n]=acc[half][q][e];
      }
  __syncthreads();

  // ---- fused LSTM update ----
  {
    const int oc=tid&63;
    const float bfv=bfp[oc], biv=bip[oc], bcv=bcp[oc], bov=bop[oc];
    for(int it=tid; it<8192; it+=512){
      int pix=it>>6;
      float f =sg[pix*256+oc];
      float i2=sg[pix*256+64+oc];
      float gg=sg[pix*256+128+oc];
      float oo=sg[pix*256+192+oc];
      f =1.f/(1.f+__expf(-(f +bfv)));
      i2=1.f/(1.f+__expf(-(i2+biv)));
      gg=2.f/(1.f+__expf(-2.f*(gg+bcv)))-1.f;
      oo=1.f/(1.f+__expf(-(oo+bov)));
      int pixg=pixbase+pix;
      size_t ci=((size_t)b*4096+pixg)*64+oc;
      float cn=g_c[ci]*f+i2*gg;
      g_c[ci]=cn;
      float hh=(2.f/(1.f+__expf(-2.f*cn))-1.f)*oo;
      if(t<TT-1){
        g_h2[dst][ci]=packh(hh);
      } else {
        out[((size_t)(b*64+oc))*4096+pixg]=hh;
        out[(size_t)NOUT+((size_t)(b*64+oc))*4096+pixg]=cn;
      }
    }
  }
}

// ---------------- host launch ----------------
extern "C" void kernel_launch(void* const* d_in, const int* in_sizes, int n_in,
                              void* d_out, int out_size)
{
  const float* x  =(const float*)d_in[0];
  const float* Wf =(const float*)d_in[1];
  const float* bf =(const float*)d_in[2];
  const float* Wi =(const float*)d_in[3];
  const float* bi =(const float*)d_in[4];
  const float* Wc =(const float*)d_in[5];
  const float* bc =(const float*)d_in[6];
  const float* Wo =(const float*)d_in[7];
  const float* bo =(const float*)d_in[8];
  float* out=(float*)d_out;

  cudaFuncSetAttribute(step_kernel, cudaFuncAttributeMaxDynamicSharedMemorySize, SMEMSZ);

  prep_w<<<(18*BLOB_EL+255)/256,256>>>(Wf,Wi,Wc,Wo);
  prep_x<<<(BB*TT*NPIX*CIN+255)/256,256>>>(x);
  zero_hc<<<(BB*NPIX*HID+255)/256,256>>>();

  for(int t=0;t<TT;t++){
    step_kernel<<<256,512,SMEMSZ>>>(t, t&1, bf,bi,bc,bo, out);
  }
}

// round 16
// speedup vs baseline: 2.5004x; 1.2850x over previous
#include <cuda_runtime.h>
#include <cuda_fp16.h>
#include <cstdint>
#include <math.h>

#define BB 8
#define TT 16
#define CIN 16
#define HID 64
#define NPIX 4096
#define NOUT (BB*HID*NPIX)

typedef unsigned int u32; typedef unsigned long long u64; typedef unsigned short u16;

// ---------------- device scratch (allocation-free) ----------------
__device__ __align__(16) u32 g_x2[BB*TT*NPIX*CIN];     // x as (lo16<<16|hi16) fp16 pair, [bt][pix][ch]
__device__ __align__(16) u32 g_h2[2][BB*NPIX*HID];     // h state, same packing, [b][pix][ch]
__device__ float g_c[BB*NPIX*HID];                     // c state fp32 [b][pix][ch]
#define BLOB_EL 22528                                  // 256*88 u16 = 45056 B
__device__ __align__(16) u16 g_Bw[18*BLOB_EL];         // 18 blobs: [tap*2+term][n(256)][k(88)]

// ---------------- helpers ----------------
__device__ __forceinline__ u32 s2u(const void* p){u32 a;asm("{ .reg .u64 t; cvta.to.shared.u64 t,%1; cvt.u32.u64 %0,t;}":"=r"(a):"l"(p));return a;}
__device__ __forceinline__ void mb_init(u32 m,u32 c){asm volatile("mbarrier.init.shared.b64 [%0],%1;"::"r"(m),"r"(c):"memory");}
__device__ __forceinline__ void mb_extx(u32 m,u32 b){asm volatile("mbarrier.arrive.expect_tx.shared.b64 _,[%0],%1;"::"r"(m),"r"(b):"memory");}
__device__ __forceinline__ void mb_arrive(u32 m){asm volatile("mbarrier.arrive.shared.b64 _,[%0];"::"r"(m):"memory");}
__device__ __forceinline__ void mb_wait(u32 m,u32 ph){
  u32 done=0;
  while(!done){
    asm volatile("{\n\t.reg .pred p;\n\tmbarrier.try_wait.parity.shared.b64 p,[%1],%2,0x989680;\n\tselp.b32 %0,1,0,p;\n\t}"
                 :"=r"(done):"r"(m),"r"(ph):"memory");
  }
}
__device__ __forceinline__ void cp_bulk(u32 dst,const void* src,u32 bytes,u32 mb){
  asm volatile("cp.async.bulk.shared::cta.global.mbarrier::complete_tx::bytes [%0],[%1],%2,[%3];"
               ::"r"(dst),"l"(src),"r"(bytes),"r"(mb):"memory");
}
#define LDSM4(r,ad) \
  asm volatile("ldmatrix.sync.aligned.m8n8.x4.shared.b16 {%0,%1,%2,%3},[%4];" \
               :"=r"((r)[0]),"=r"((r)[1]),"=r"((r)[2]),"=r"((r)[3]):"r"(ad))
#define MMA(c,a,b0,b1) \
  asm volatile("mma.sync.aligned.m16n8k16.row.col.f32.f16.f16.f32 {%0,%1,%2,%3},{%4,%5,%6,%7},{%8,%9},{%0,%1,%2,%3};" \
               :"+f"((c)[0]),"+f"((c)[1]),"+f"((c)[2]),"+f"((c)[3]) \
               :"r"((a)[0]),"r"((a)[1]),"r"((a)[2]),"r"((a)[3]),"r"(b0),"r"(b1))

__device__ __forceinline__ u32 packh(float v){
  __half h=__float2half_rn(v);
  u16 hb=__half_as_ushort(h);
  u16 lb=__half_as_ushort(__float2half_rn(v-__half2float(h)));
  return ((u32)lb<<16)|hb;
}

// ---------------- prep kernels ----------------
__global__ void prep_w(const float* __restrict__ Wf,const float* __restrict__ Wi,
                       const float* __restrict__ Wc,const float* __restrict__ Wo){
  int id=blockIdx.x*blockDim.x+threadIdx.x;
  if(id>=18*BLOB_EL) return;
  int k=id%88, n=(id/88)&255, j=id/BLOB_EL;
  int tap=j>>1, term=j&1;
  float v=0.f;
  if(k<80 && (n<192 || tap==4)){
    int gate=n>>6, oc=n&63;
    if(gate==0) v=Wf[(oc*80+k)*9+tap];
    else if(gate==1) v=Wi[(oc*80+k)*9+tap];
    else if(gate==2) v=Wc[(oc*80+k)*9+tap];
    else v=Wo[oc*80+k];
  }
  __half h=__float2half_rn(v);
  u16 val=(term==0)?__half_as_ushort(h):__half_as_ushort(__float2half_rn(v-__half2float(h)));
  g_Bw[id]=val;
}

__global__ void prep_x(const float* __restrict__ x){
  int id=blockIdx.x*blockDim.x+threadIdx.x;
  if(id>=BB*TT*NPIX*CIN) return;
  int c=id&15, pix=(id>>4)&4095, bt=id>>16;
  g_x2[id]=packh(x[((size_t)bt*16+c)*4096+pix]);
}

__global__ void zero_hc(){
  int id=blockIdx.x*blockDim.x+threadIdx.x;
  if(id<BB*NPIX*HID){ g_h2[0][id]=0u; g_c[id]=0.f; }
}

// ---------------- fused step kernel ----------------
// smem: A-hi [264][88]u16 @0 (46464B), ring 4x45056 @46464,
//       full mbar[4] @226688, empty mbar[4] @226720
#define RING   46464
#define BLOB   45056
#define MB_F   226688
#define MB_E   226720
#define SMEMSZ 226752

__global__ __launch_bounds__(512,1) void step_kernel(int t,int src,
     const float* __restrict__ bfp,const float* __restrict__ bip,
     const float* __restrict__ bcp,const float* __restrict__ bop,
     float* __restrict__ out)
{
  extern __shared__ __align__(1024) unsigned char smem[];
  const u32 sb=s2u(smem);
  const int tid=threadIdx.x, lane=tid&31, wid=tid>>5;
  const int blk=blockIdx.x, b=blk>>5, ty=blk&31;
  const int pixbase=ty*128;
  const int dst=src^1;

  // ---- init barriers, then prime ring slots 0..3 ----
  if(tid==0){
    for(int m=0;m<4;m++){ mb_init(sb+MB_F+8*m,1); mb_init(sb+MB_E+8*m,16); }
  }
  __syncthreads();
  if(tid==0){
    for(int j=0;j<4;j++){
      mb_extx(sb+MB_F+8*j,BLOB);
      cp_bulk(sb+RING+(u32)j*BLOB,(const void*)(g_Bw+(size_t)j*BLOB_EL),BLOB,sb+MB_F+8*j);
    }
  }

  // ---- stage A patch (hi plane only): 4 rows x 66 cols x 80 ch ----
  {
    u16* aHi=(u16*)smem;
    for(int id=tid; id<264*80; id+=512){
      int s=id/80, ch=id-80*s;
      int r=s/66, c2=s-66*r;
      int gy=ty*2-1+r, gx=c2-1;
      u32 v=0u;
      if((unsigned)gy<64u && (unsigned)gx<64u){
        int pix=gy*64+gx;
        v=(ch<16)? g_x2[((size_t)(b*16+t)*4096+pix)*16+ch]
                 : g_h2[src][((size_t)b*4096+pix)*64+(ch-16)];
      }
      aHi[s*88+ch]=(u16)(v&0xffffu);
    }
  }
  __syncthreads();

  // ---- warp roles: warpM = wid>>2 (32 pix), warpN = (warpM + wid&3)&3 ----
  const int warpM=wid>>2;
  const int warpN=(warpM+(wid&3))&3;
  int nb[4];
  if(warpN<2){ nb[0]=warpN*64; nb[1]=nb[0]+16; nb[2]=nb[0]+32; nb[3]=nb[0]+48; }
  else { int g0=128+(warpN-2)*32, o0=192+(warpN-2)*32;
         nb[0]=g0; nb[1]=g0+16; nb[2]=o0; nb[3]=o0+16; }
  const u32 aofs=(u32)((lane&15)*176+(lane>>4)*16);
  const u32 bofs=(u32)(((lane&7)+((lane>>4)&1)*8)*176+((lane>>3)&1)*16);
  u32 hofs[2];
#pragma unroll
  for(int half=0;half<2;half++){
    int m0=warpM*32+half*16;
    hofs[half]=(u32)(((m0>>6)*66+(m0&63))*176)+aofs;
  }

  float acc[2][8][4];
#pragma unroll
  for(int h2=0;h2<2;h2++)
#pragma unroll
    for(int q=0;q<8;q++)
#pragma unroll
      for(int e=0;e<4;e++) acc[h2][q][e]=0.f;

  // ---- main loop: 18 blobs, one uniform Ah-term pass per blob ----
  for(int j=0;j<18;j++){
    const int slot=j&3, ph=(j>>2)&1, tap=j>>1;
    mb_wait(sb+MB_F+8*(u32)slot,(u32)ph);
    const u32 bb=sb+RING+(u32)slot*BLOB;
    const int dy=tap/3-1, dx=tap%3-1;
    const u32 taprow=(u32)(((dy+1)*66+(dx+1))*176);
    const int npA=(warpN<2||tap==4)?4:2;
#pragma unroll
    for(int kc=0;kc<5;kc++){
      u32 bf_[4][4];
#pragma unroll
      for(int p=0;p<4;p++){
        if(p<npA){
          LDSM4(bf_[p], bb+(u32)nb[p]*176u+(u32)kc*32u+bofs);
        }
      }
#pragma unroll
      for(int half=0;half<2;half++){
        u32 a4[4];
        LDSM4(a4, sb+hofs[half]+taprow+(u32)kc*32u);
#pragma unroll
        for(int p=0;p<4;p++){
          if(p<npA){
            MMA(acc[half][2*p],   a4, bf_[p][0],bf_[p][1]);
            MMA(acc[half][2*p+1], a4, bf_[p][2],bf_[p][3]);
          }
        }
      }
    }
    if(lane==0) mb_arrive(sb+MB_E+8*(u32)slot);
    if(wid==slot && lane==0 && j+4<18){
      mb_wait(sb+MB_E+8*(u32)slot,(u32)ph);
      mb_extx(sb+MB_F+8*(u32)slot,BLOB);
      cp_bulk(bb,(const void*)(g_Bw+(size_t)(j+4)*BLOB_EL),BLOB,sb+MB_F+8*(u32)slot);
    }
  }

  // ---- cross-warp gate exchange via smem (reuse A/ring region) ----
  __syncthreads();
  float* sg=(float*)smem;   // [128 pix][256 n] f32 = 131072 B
#pragma unroll
  for(int half=0;half<2;half++)
#pragma unroll
    for(int q=0;q<8;q++)
#pragma unroll
      for(int e=0;e<4;e++){
        int pix=warpM*32+half*16+(lane>>2)+((e>>1)*8);
        int n=nb[q>>1]+(q&1)*8+(lane&3)*2+(e&1);
        sg[pix*256+n]=acc[half][q][e];
      }
  __syncthreads();

  // ---- fused LSTM update ----
  {
    const int oc=tid&63;
    const float bfv=bfp[oc], biv=bip[oc], bcv=bcp[oc], bov=bop[oc];
    for(int it=tid; it<8192; it+=512){
      int pix=it>>6;
      float f =sg[pix*256+oc];
      float i2=sg[pix*256+64+oc];
      float gg=sg[pix*256+128+oc];
      float oo=sg[pix*256+192+oc];
      f =1.f/(1.f+__expf(-(f +bfv)));
      i2=1.f/(1.f+__expf(-(i2+biv)));
      gg=2.f/(1.f+__expf(-2.f*(gg+bcv)))-1.f;
      oo=1.f/(1.f+__expf(-(oo+bov)));
      int pixg=pixbase+pix;
      size_t ci=((size_t)b*4096+pixg)*64+oc;
      float cn=g_c[ci]*f+i2*gg;
      g_c[ci]=cn;
      float hh=(2.f/(1.f+__expf(-2.f*cn))-1.f)*oo;
      if(t<TT-1){
        g_h2[dst][ci]=packh(hh);
      } else {
        out[((size_t)(b*64+oc))*4096+pixg]=hh;
        out[(size_t)NOUT+((size_t)(b*64+oc))*4096+pixg]=cn;
      }
    }
  }
}

// ---------------- host launch ----------------
extern "C" void kernel_launch(void* const* d_in, const int* in_sizes, int n_in,
                              void* d_out, int out_size)
{
  const float* x  =(const float*)d_in[0];
  const float* Wf =(const float*)d_in[1];
  const float* bf =(const float*)d_in[2];
  const float* Wi =(const float*)d_in[3];
  const float* bi =(const float*)d_in[4];
  const float* Wc =(const float*)d_in[5];
  const float* bc =(const float*)d_in[6];
  const float* Wo =(const float*)d_in[7];
  const float* bo =(const float*)d_in[8];
  float* out=(float*)d_out;

  cudaFuncSetAttribute(step_kernel, cudaFuncAttributeMaxDynamicSharedMemorySize, SMEMSZ);

  prep_w<<<(18*BLOB_EL+255)/256,256>>>(Wf,Wi,Wc,Wo);
  prep_x<<<(BB*TT*NPIX*CIN+255)/256,256>>>(x);
  zero_hc<<<(BB*NPIX*HID+255)/256,256>>>();

  for(int t=0;t<TT;t++){
    step_kernel<<<256,512,SMEMSZ>>>(t, t&1, bf,bi,bc,bo, out);
  }
}

// round 17
// speedup vs baseline: 2.7696x; 1.1077x over previous
#include <cuda_runtime.h>
#include <cuda_fp16.h>
#include <cstdint>
#include <math.h>

#define BB 8
#define TT 16
#define CIN 16
#define HID 64
#define NPIX 4096
#define NOUT (BB*HID*NPIX)

typedef unsigned int u32; typedef unsigned long long u64; typedef unsigned short u16;

// ---------------- device scratch (allocation-free) ----------------
__device__ __align__(16) u32 g_x2[BB*TT*NPIX*CIN];     // x as (lo16<<16|hi16) fp16 pair, [bt][pix][ch]
__device__ __align__(16) u32 g_h2[2][BB*NPIX*HID];     // h state, same packing, [b][pix][ch]
__device__ float g_c[BB*NPIX*HID];                     // c state fp32 [b][pix][ch]
#define CBLOB_EL 16896                                 // 192*88 u16 = 33792 B
#define OG_EL    5632                                  // 64*88 u16  = 11264 B
__device__ __align__(16) u16 g_Bw[18*CBLOB_EL+OG_EL];  // 18 conv blobs + o-gate(hi) blob

// ---------------- helpers ----------------
__device__ __forceinline__ u32 s2u(const void* p){u32 a;asm("{ .reg .u64 t; cvta.to.shared.u64 t,%1; cvt.u32.u64 %0,t;}":"=r"(a):"l"(p));return a;}
__device__ __forceinline__ void mb_init(u32 m,u32 c){asm volatile("mbarrier.init.shared.b64 [%0],%1;"::"r"(m),"r"(c):"memory");}
__device__ __forceinline__ void mb_extx(u32 m,u32 b){asm volatile("mbarrier.arrive.expect_tx.shared.b64 _,[%0],%1;"::"r"(m),"r"(b):"memory");}
__device__ __forceinline__ void mb_arrive(u32 m){asm volatile("mbarrier.arrive.shared.b64 _,[%0];"::"r"(m):"memory");}
__device__ __forceinline__ void mb_wait(u32 m,u32 ph){
  u32 done=0;
  while(!done){
    asm volatile("{\n\t.reg .pred p;\n\tmbarrier.try_wait.parity.shared.b64 p,[%1],%2,0x989680;\n\tselp.b32 %0,1,0,p;\n\t}"
                 :"=r"(done):"r"(m),"r"(ph):"memory");
  }
}
__device__ __forceinline__ void cp_bulk(u32 dst,const void* src,u32 bytes,u32 mb){
  asm volatile("cp.async.bulk.shared::cta.global.mbarrier::complete_tx::bytes [%0],[%1],%2,[%3];"
               ::"r"(dst),"l"(src),"r"(bytes),"r"(mb):"memory");
}
#define LDSM4(r,ad) \
  asm volatile("ldmatrix.sync.aligned.m8n8.x4.shared.b16 {%0,%1,%2,%3},[%4];" \
               :"=r"((r)[0]),"=r"((r)[1]),"=r"((r)[2]),"=r"((r)[3]):"r"(ad))
#define MMA(c,a,b0,b1) \
  asm volatile("mma.sync.aligned.m16n8k16.row.col.f32.f16.f16.f32 {%0,%1,%2,%3},{%4,%5,%6,%7},{%8,%9},{%0,%1,%2,%3};" \
               :"+f"((c)[0]),"+f"((c)[1]),"+f"((c)[2]),"+f"((c)[3]) \
               :"r"((a)[0]),"r"((a)[1]),"r"((a)[2]),"r"((a)[3]),"r"(b0),"r"(b1))

__device__ __forceinline__ u32 packh(float v){
  __half h=__float2half_rn(v);
  u16 hb=__half_as_ushort(h);
  u16 lb=__half_as_ushort(__float2half_rn(v-__half2float(h)));
  return ((u32)lb<<16)|hb;
}

// ---------------- prep kernels ----------------
__global__ void prep_w(const float* __restrict__ Wf,const float* __restrict__ Wi,
                       const float* __restrict__ Wc,const float* __restrict__ Wo){
  int id=blockIdx.x*blockDim.x+threadIdx.x;
  if(id>=18*CBLOB_EL+OG_EL) return;
  float v=0.f; int term=0;
  if(id<18*CBLOB_EL){
    int j=id/CBLOB_EL, r=id%CBLOB_EL, n=r/88, k=r%88;
    int tap=j>>1; term=j&1;
    if(k<80){
      int gate=n>>6, oc=n&63;
      if(gate==0) v=Wf[(oc*80+k)*9+tap];
      else if(gate==1) v=Wi[(oc*80+k)*9+tap];
      else v=Wc[(oc*80+k)*9+tap];
    }
  } else {
    int r=id-18*CBLOB_EL, n=r/88, k=r%88;
    if(k<80) v=Wo[n*80+k];
  }
  __half h=__float2half_rn(v);
  u16 val=(term==0)?__half_as_ushort(h):__half_as_ushort(__float2half_rn(v-__half2float(h)));
  g_Bw[id]=val;
}

__global__ void prep_x(const float* __restrict__ x){
  int id=blockIdx.x*blockDim.x+threadIdx.x;
  if(id>=BB*TT*NPIX*CIN) return;
  int c=id&15, pix=(id>>4)&4095, bt=id>>16;
  g_x2[id]=packh(x[((size_t)bt*16+c)*4096+pix]);
}

__global__ void zero_hc(){
  int id=blockIdx.x*blockDim.x+threadIdx.x;
  if(id<BB*NPIX*HID){ g_h2[0][id]=0u; g_c[id]=0.f; }
}

// ---------------- fused step kernel ----------------
// smem: A-hi [264][88]u16 @0 (46464B), ring 5x33792 @46464 (ends 215424),
//       ogate blob @215424 (11264B), full mbar[5] @226688, empty mbar[5] @226728,
//       og mbar @226768
#define RING   46464
#define CBLOB  33792
#define OGB    215424
#define MB_F   226688
#define MB_E   226728
#define MB_O   226768
#define SMEMSZ 226784

__global__ __launch_bounds__(512,1) void step_kernel(int t,int src,
     const float* __restrict__ bfp,const float* __restrict__ bip,
     const float* __restrict__ bcp,const float* __restrict__ bop,
     float* __restrict__ out)
{
  extern __shared__ __align__(1024) unsigned char smem[];
  const u32 sb=s2u(smem);
  const int tid=threadIdx.x, lane=tid&31, wid=tid>>5;
  const int blk=blockIdx.x, b=blk>>5, ty=blk&31;
  const int pixbase=ty*128;
  const int dst=src^1;

  // ---- init barriers, prime ring slots 0..4 + ogate ----
  if(tid==0){
    for(int m=0;m<5;m++){ mb_init(sb+MB_F+8*m,1); mb_init(sb+MB_E+8*m,16); }
    mb_init(sb+MB_O,1);
  }
  __syncthreads();
  if(tid==0){
    for(int j=0;j<5;j++){
      mb_extx(sb+MB_F+8*j,CBLOB);
      cp_bulk(sb+RING+(u32)j*CBLOB,(const void*)(g_Bw+(size_t)j*CBLOB_EL),CBLOB,sb+MB_F+8*j);
    }
    mb_extx(sb+MB_O,OG_EL*2);
    cp_bulk(sb+OGB,(const void*)(g_Bw+18*CBLOB_EL),OG_EL*2,sb+MB_O);
  }

  // ---- stage A patch (hi plane only): 4 rows x 66 cols x 80 ch ----
  {
    u16* aHi=(u16*)smem;
    for(int id=tid; id<264*80; id+=512){
      int s=id/80, ch=id-80*s;
      int r=s/66, c2=s-66*r;
      int gy=ty*2-1+r, gx=c2-1;
      u32 v=0u;
      if((unsigned)gy<64u && (unsigned)gx<64u){
        int pix=gy*64+gx;
        v=(ch<16)? g_x2[((size_t)(b*16+t)*4096+pix)*16+ch]
                 : g_h2[src][((size_t)b*4096+pix)*64+(ch-16)];
      }
      aHi[s*88+ch]=(u16)(v&0xffffu);
    }
  }
  __syncthreads();

  // ---- warp roles: warpM = wid>>2 (32 pix), warpN = (warpM + wid&3)&3 ----
  const int warpM=wid>>2;
  const int warpN=(warpM+(wid&3))&3;
  const u32 aofs=(u32)((lane&15)*176+(lane>>4)*16);
  const u32 bofs=(u32)(((lane&7)+((lane>>4)&1)*8)*176+((lane>>3)&1)*16);
  u32 hofs[2];
#pragma unroll
  for(int half=0;half<2;half++){
    int m0=warpM*32+half*16;
    hofs[half]=(u32)(((m0>>6)*66+(m0&63))*176)+aofs;
  }
  u32 boff[3];
#pragma unroll
  for(int tt=0;tt<3;tt++) boff[tt]=(u32)(warpN*48+tt*16)*176u+bofs;

  // acc: q0..5 conv (48 cols), q6..7 o-gate (16 cols)
  float acc[2][8][4];
#pragma unroll
  for(int h2=0;h2<2;h2++)
#pragma unroll
    for(int q=0;q<8;q++)
#pragma unroll
      for(int e=0;e<4;e++) acc[h2][q][e]=0.f;

  // ---- main loop: 18 uniform conv blobs, kc-pipelined frags ----
  for(int j=0;j<18;j++){
    const int slot=j%5, ph=(j/5)&1, tap=j>>1;
    mb_wait(sb+MB_F+8*(u32)slot,(u32)ph);
    const u32 bb=sb+RING+(u32)slot*CBLOB;
    const int dy=tap/3-1, dx=tap%3-1;
    const u32 abase0=sb+hofs[0]+(u32)(((dy+1)*66+(dx+1))*176);
    const u32 abase1=sb+hofs[1]+(u32)(((dy+1)*66+(dx+1))*176);

    u32 bfr[2][3][4], afr[2][2][4];
#pragma unroll
    for(int tt=0;tt<3;tt++) LDSM4(bfr[0][tt], bb+boff[tt]);
    LDSM4(afr[0][0], abase0);
    LDSM4(afr[0][1], abase1);
#pragma unroll
    for(int kc=0;kc<5;kc++){
      const int cur=kc&1, nxt=cur^1;
      if(kc<4){
        const u32 ko=(u32)(kc+1)*32u;
#pragma unroll
        for(int tt=0;tt<3;tt++) LDSM4(bfr[nxt][tt], bb+boff[tt]+ko);
        LDSM4(afr[nxt][0], abase0+ko);
        LDSM4(afr[nxt][1], abase1+ko);
      }
#pragma unroll
      for(int tt=0;tt<3;tt++){
#pragma unroll
        for(int half=0;half<2;half++){
          MMA(acc[half][2*tt],   afr[cur][half], bfr[cur][tt][0],bfr[cur][tt][1]);
          MMA(acc[half][2*tt+1], afr[cur][half], bfr[cur][tt][2],bfr[cur][tt][3]);
        }
      }
    }
    if(lane==0) mb_arrive(sb+MB_E+8*(u32)slot);
    if(wid==slot && lane==0 && j+5<18){
      mb_wait(sb+MB_E+8*(u32)slot,(u32)ph);
      mb_extx(sb+MB_F+8*(u32)slot,CBLOB);
      cp_bulk(bb,(const void*)(g_Bw+(size_t)(j+5)*CBLOB_EL),CBLOB,sb+MB_F+8*(u32)slot);
    }
  }

  // ---- o-gate phase: hi-only blob, center-tap A, N=64 (16/warpN) ----
  {
    mb_wait(sb+MB_O,0u);
    const u32 ob=sb+OGB+(u32)(warpN*16)*176u+bofs;
    const u32 abase0=sb+hofs[0]+(u32)((1*66+1)*176);
    const u32 abase1=sb+hofs[1]+(u32)((1*66+1)*176);
#pragma unroll
    for(int kc=0;kc<5;kc++){
      u32 bh[4], a0[4], a1[4];
      const u32 ko=(u32)kc*32u;
      LDSM4(bh, ob+ko);
      LDSM4(a0, abase0+ko);
      LDSM4(a1, abase1+ko);
      MMA(acc[0][6], a0, bh[0],bh[1]);
      MMA(acc[0][7], a0, bh[2],bh[3]);
      MMA(acc[1][6], a1, bh[0],bh[1]);
      MMA(acc[1][7], a1, bh[2],bh[3]);
    }
  }

  // ---- cross-warp gate exchange via smem (reuse A/ring region) ----
  __syncthreads();
  float* sg=(float*)smem;   // [128 pix][256 n] f32 = 131072 B
#pragma unroll
  for(int half=0;half<2;half++){
#pragma unroll
    for(int q=0;q<6;q++)
#pragma unroll
      for(int e=0;e<4;e++){
        int pix=warpM*32+half*16+(lane>>2)+((e>>1)*8);
        int n=warpN*48+(q>>1)*16+(q&1)*8+(lane&3)*2+(e&1);
        sg[pix*256+n]=acc[half][q][e];
      }
#pragma unroll
    for(int q=6;q<8;q++)
#pragma unroll
      for(int e=0;e<4;e++){
        int pix=warpM*32+half*16+(lane>>2)+((e>>1)*8);
        int n=192+warpN*16+(q-6)*8+(lane&3)*2+(e&1);
        sg[pix*256+n]=acc[half][q][e];
      }
  }
  __syncthreads();

  // ---- fused LSTM update ----
  {
    const int oc=tid&63;
    const float bfv=bfp[oc], biv=bip[oc], bcv=bcp[oc], bov=bop[oc];
    for(int it=tid; it<8192; it+=512){
      int pix=it>>6;
      float f =sg[pix*256+oc];
      float i2=sg[pix*256+64+oc];
      float gg=sg[pix*256+128+oc];
      float oo=sg[pix*256+192+oc];
      f =1.f/(1.f+__expf(-(f +bfv)));
      i2=1.f/(1.f+__expf(-(i2+biv)));
      gg=2.f/(1.f+__expf(-2.f*(gg+bcv)))-1.f;
      oo=1.f/(1.f+__expf(-(oo+bov)));
      int pixg=pixbase+pix;
      size_t ci=((size_t)b*4096+pixg)*64+oc;
      float cn=g_c[ci]*f+i2*gg;
      g_c[ci]=cn;
      float hh=(2.f/(1.f+__expf(-2.f*cn))-1.f)*oo;
      if(t<TT-1){
        g_h2[dst][ci]=packh(hh);
      } else {
        out[((size_t)(b*64+oc))*4096+pixg]=hh;
        out[(size_t)NOUT+((size_t)(b*64+oc))*4096+pixg]=cn;
      }
    }
  }
}

// ---------------- host launch ----------------
extern "C" void kernel_launch(void* const* d_in, const int* in_sizes, int n_in,
                              void* d_out, int out_size)
{
  const float* x  =(const float*)d_in[0];
  const float* Wf =(const float*)d_in[1];
  const float* bf =(const float*)d_in[2];
  const float* Wi =(const float*)d_in[3];
  const float* bi =(const float*)d_in[4];
  const float* Wc =(const float*)d_in[5];
  const float* bc =(const float*)d_in[6];
  const float* Wo =(const float*)d_in[7];
  const float* bo =(const float*)d_in[8];
  float* out=(float*)d_out;

  cudaFuncSetAttribute(step_kernel, cudaFuncAttributeMaxDynamicSharedMemorySize, SMEMSZ);

  prep_w<<<(18*CBLOB_EL+OG_EL+255)/256,256>>>(Wf,Wi,Wc,Wo);
  prep_x<<<(BB*TT*NPIX*CIN+255)/256,256>>>(x);
  zero_hc<<<(BB*NPIX*HID+255)/256,256>>>();

  for(int t=0;t<TT;t++){
    step_kernel<<<256,512,SMEMSZ>>>(t, t&1, bf,bi,bc,bo, out);
  }
}